// round 1
// baseline (speedup 1.0000x reference)
#include <cuda_runtime.h>
#include <math.h>

#define NN 10000
#define NE 320000
#define H  256

// ---------------- scratch (static device allocations, ~55MB) ----------------
__device__ float g_Pa[NN * H];
__device__ float g_Pb[NN * H];
__device__ float g_agg[NN * H];
__device__ float g_q[NN * H];
__device__ float g_h1[NN * H];
__device__ float g_cd[NE * 3];
__device__ float g_aggx[NN * 3];

__device__ __forceinline__ float sigmf(float v) { return 1.0f / (1.0f + __expf(-v)); }
__device__ __forceinline__ float siluf(float v) { return v / (1.0f + __expf(-v)); }

// ---------------- coord2diff ----------------
__global__ void coord_diff_kernel(const int* __restrict__ ei, const float* __restrict__ x,
                                  float* __restrict__ cd) {
    int e = blockIdx.x * blockDim.x + threadIdx.x;
    if (e >= NE) return;
    int r = ei[e], c = ei[NE + e];
    float dx = x[r * 3 + 0] - x[c * 3 + 0];
    float dy = x[r * 3 + 1] - x[c * 3 + 1];
    float dz = x[r * 3 + 2] - x[c * 3 + 2];
    float rad = dx * dx + dy * dy + dz * dz;
    float inv = 1.0f / (sqrtf(rad + 1e-8f) + 1.0f);
    cd[e * 3 + 0] = dx * inv;
    cd[e * 3 + 1] = dy * inv;
    cd[e * 3 + 2] = dz * inv;
}

// ---------------- generic node GEMM: C = [act](A1@B1 [+ A2@B2] + bias) [+ resid] ----------------
// All B matrices are [K,256] row-major; C is [M,256].
__global__ __launch_bounds__(256) void node_gemm(
    const float* __restrict__ A1, const float* __restrict__ B1, int K1,
    const float* __restrict__ A2, const float* __restrict__ B2,
    const float* __restrict__ bias, const float* __restrict__ resid,
    float* __restrict__ C, int M, int act) {
    __shared__ float As[16][64];
    __shared__ float Bs[16][64];
    int tid = threadIdx.x;
    int m0 = blockIdx.x * 64, n0 = blockIdx.y * 64;
    int ty = tid >> 4, tx = tid & 15;

    int ar = tid >> 2, ac = (tid & 3) << 2;   // A tile load: row ar (0..63), k off ac
    int br = tid >> 4, bc = (tid & 15) << 2;  // B tile load: k row br (0..15), col bc
    int arr = min(m0 + ar, M - 1);

    float acc[4][4] = {};
    int npass = A2 ? 2 : 1;
    for (int pass = 0; pass < npass; ++pass) {
        const float* A = pass ? A2 : A1;
        const float* B = pass ? B2 : B1;
        int K = pass ? H : K1;
        for (int k0 = 0; k0 < K; k0 += 16) {
            float4 av = *(const float4*)&A[(size_t)arr * K + k0 + ac];
            float4 bv = *(const float4*)&B[(size_t)(k0 + br) * H + n0 + bc];
            __syncthreads();
            As[ac + 0][ar] = av.x;
            As[ac + 1][ar] = av.y;
            As[ac + 2][ar] = av.z;
            As[ac + 3][ar] = av.w;
            *(float4*)&Bs[br][bc] = bv;
            __syncthreads();
#pragma unroll
            for (int k = 0; k < 16; ++k) {
                float4 a4 = *(const float4*)&As[k][ty << 2];
                float4 b4 = *(const float4*)&Bs[k][tx << 2];
                float aa[4] = {a4.x, a4.y, a4.z, a4.w};
                float bb[4] = {b4.x, b4.y, b4.z, b4.w};
#pragma unroll
                for (int i = 0; i < 4; ++i)
#pragma unroll
                    for (int j = 0; j < 4; ++j) acc[i][j] += aa[i] * bb[j];
            }
        }
    }
    int col = n0 + (tx << 2);
    float4 bb4 = make_float4(0.f, 0.f, 0.f, 0.f);
    if (bias) bb4 = *(const float4*)&bias[col];
#pragma unroll
    for (int i = 0; i < 4; ++i) {
        int row = m0 + (ty << 2) + i;
        if (row >= M) continue;
        float v[4] = {acc[i][0] + bb4.x, acc[i][1] + bb4.y, acc[i][2] + bb4.z, acc[i][3] + bb4.w};
        if (act == 1) {
#pragma unroll
            for (int j = 0; j < 4; ++j) v[j] = siluf(v[j]);
        }
        if (resid) {
            float4 rv = *(const float4*)&resid[(size_t)row * H + col];
            v[0] += rv.x; v[1] += rv.y; v[2] += rv.z; v[3] += rv.w;
        }
        *(float4*)&C[(size_t)row * H + col] = make_float4(v[0], v[1], v[2], v[3]);
    }
}

// ---------------- fused edge kernel ----------------
// Per 64-edge tile: u = silu(Pa[row] + Pb[col] + ea@W1tail + b1)  (smem)
// GEMM: acc = u @ W2  (64x256x256)
// GCL epilogue:  mij = silu(acc+b2); att = sigmoid(mij.aw + ab)/100; atomicAdd agg[row] += mij*att
// COORD epilogue: t2 = silu(acc+b2); phi = (t2.cw3)/100; atomicAdd aggx[row] += coord_diff*phi
#define SMEM_EDGE ((64 * H + H * 36) * 4 + 64 * 4 * 4)

template <bool COORD>
__global__ __launch_bounds__(256, 2) void edge_kernel(
    const int* __restrict__ ei, const float* __restrict__ eattr,
    const float* __restrict__ Pa, const float* __restrict__ Pb,
    const float* __restrict__ wtail, const float* __restrict__ b1,
    const float* __restrict__ W2, const float* __restrict__ b2,
    const float* __restrict__ wv, const float* __restrict__ ab,
    float* __restrict__ agg, const float* __restrict__ cd) {
    extern __shared__ float sm[];
    float* u_s = sm;                       // 64*256
    float* W2t = sm + 64 * H;              // 256*36 (k-transposed, padded)
    int* ridx = (int*)(W2t + H * 36);      // 64
    int* cidx = ridx + 64;
    float* ea0 = (float*)(cidx + 64);
    float* ea1 = ea0 + 64;

    int tid = threadIdx.x;
    int e0 = blockIdx.x * 64;
    if (tid < 64) {
        int e = e0 + tid;
        ridx[tid] = ei[e];
        cidx[tid] = ei[NE + e];
        float2 a = ((const float2*)eattr)[e];
        ea0[tid] = a.x;
        ea1[tid] = a.y;
    }
    __syncthreads();

    // phase A: build u = silu(t1)
#pragma unroll
    for (int it = 0; it < 16; ++it) {
        int idx = it * 256 + tid;          // 0..4095
        int e = idx >> 6;
        int c = (idx & 63) << 2;
        int r = ridx[e], cl = cidx[e];
        float4 pa = *(const float4*)&Pa[(size_t)r * H + c];
        float4 pb = *(const float4*)&Pb[(size_t)cl * H + c];
        float4 w0 = *(const float4*)&wtail[c];
        float4 w1 = *(const float4*)&wtail[H + c];
        float4 bv = *(const float4*)&b1[c];
        float a0 = ea0[e], a1 = ea1[e];
        float4 t;
        t.x = siluf(pa.x + pb.x + a0 * w0.x + a1 * w1.x + bv.x);
        t.y = siluf(pa.y + pb.y + a0 * w0.y + a1 * w1.y + bv.y);
        t.z = siluf(pa.z + pb.z + a0 * w0.z + a1 * w1.z + bv.z);
        t.w = siluf(pa.w + pb.w + a0 * w0.w + a1 * w1.w + bv.w);
        *(float4*)&u_s[e * H + c] = t;
    }
    __syncthreads();

    // phase B: GEMM u(64x256) @ W2(256x256)
    int ty = tid >> 5, tx = tid & 31;  // rows ty*8..+7, cols tx+32j
    float acc[8][8] = {};
    for (int kb = 0; kb < 8; ++kb) {
#pragma unroll
        for (int it = 0; it < 8; ++it) {
            int idx4 = it * 256 + tid;     // 0..2047
            int kl = idx4 >> 6;            // 0..31
            int c4 = (idx4 & 63) << 2;
            float4 v = *(const float4*)&W2[(size_t)(kb * 32 + kl) * H + c4];
            W2t[(c4 + 0) * 36 + kl] = v.x;
            W2t[(c4 + 1) * 36 + kl] = v.y;
            W2t[(c4 + 2) * 36 + kl] = v.z;
            W2t[(c4 + 3) * 36 + kl] = v.w;
        }
        __syncthreads();
#pragma unroll
        for (int k = 0; k < 32; k += 4) {
            float4 b4[8];
#pragma unroll
            for (int j = 0; j < 8; ++j) b4[j] = *(const float4*)&W2t[(tx + 32 * j) * 36 + k];
#pragma unroll
            for (int i = 0; i < 8; ++i) {
                float4 a4 = *(const float4*)&u_s[(ty * 8 + i) * H + kb * 32 + k];
#pragma unroll
                for (int j = 0; j < 8; ++j)
                    acc[i][j] += a4.x * b4[j].x + a4.y * b4[j].y + a4.z * b4[j].z + a4.w * b4[j].w;
            }
        }
        __syncthreads();
    }

    // epilogue
    float bcol[8], wc[8];
#pragma unroll
    for (int j = 0; j < 8; ++j) {
        bcol[j] = b2[tx + 32 * j];
        wc[j] = wv[tx + 32 * j];
    }
    float abv = COORD ? 0.f : ab[0];
#pragma unroll
    for (int i = 0; i < 8; ++i) {
        float p = 0.f;
#pragma unroll
        for (int j = 0; j < 8; ++j) {
            float v = siluf(acc[i][j] + bcol[j]);
            acc[i][j] = v;
            p += v * wc[j];
        }
#pragma unroll
        for (int off = 16; off; off >>= 1) p += __shfl_xor_sync(0xffffffffu, p, off);
        int er = ty * 8 + i;
        int r = ridx[er];
        if (COORD) {
            float phi = p * 0.01f;  // fold /NORM_FACTOR
            if (tx < 3) {
                float c = cd[(size_t)(e0 + er) * 3 + tx];
                atomicAdd(&agg[(size_t)r * 3 + tx], c * phi);
            }
        } else {
            float att = sigmf(p + abv) * 0.01f;  // fold /NORM_FACTOR
#pragma unroll
            for (int j = 0; j < 8; ++j)
                atomicAdd(&agg[(size_t)r * H + tx + 32 * j], acc[i][j] * att);
        }
    }
}

__global__ void x_final_kernel(const float* __restrict__ x, const float* __restrict__ aggx,
                               float* __restrict__ out) {
    int i = blockIdx.x * blockDim.x + threadIdx.x;
    if (i < NN * 3) out[i] = x[i] + aggx[i];
}

// ---------------- launch ----------------
extern "C" void kernel_launch(void* const* d_in, const int* in_sizes, int n_in,
                              void* d_out, int out_size) {
    const float* h0 = (const float*)d_in[0];
    const float* x = (const float*)d_in[1];
    const int* ei = (const int*)d_in[2];
    const float* ea = (const float*)d_in[3];
    const float* p[2][10];
    for (int l = 0; l < 2; ++l)
        for (int i = 0; i < 10; ++i) p[l][i] = (const float*)d_in[4 + l * 10 + i];
    // p[l]: 0 ew1, 1 eb1, 2 ew2, 3 eb2, 4 nw1, 5 nb1, 6 nw2, 7 nb2, 8 aw, 9 ab
    const float* cw1 = (const float*)d_in[24];
    const float* cb1 = (const float*)d_in[25];
    const float* cw2 = (const float*)d_in[26];
    const float* cb2 = (const float*)d_in[27];
    const float* cw3 = (const float*)d_in[28];

    float* outh = (float*)d_out;
    float* outx = outh + (size_t)NN * H;

    float *Pa, *Pb, *agg, *q, *h1, *cdp, *aggx;
    cudaGetSymbolAddress((void**)&Pa, g_Pa);
    cudaGetSymbolAddress((void**)&Pb, g_Pb);
    cudaGetSymbolAddress((void**)&agg, g_agg);
    cudaGetSymbolAddress((void**)&q, g_q);
    cudaGetSymbolAddress((void**)&h1, g_h1);
    cudaGetSymbolAddress((void**)&cdp, g_cd);
    cudaGetSymbolAddress((void**)&aggx, g_aggx);

    cudaFuncSetAttribute(edge_kernel<false>, cudaFuncAttributeMaxDynamicSharedMemorySize, SMEM_EDGE);
    cudaFuncSetAttribute(edge_kernel<true>, cudaFuncAttributeMaxDynamicSharedMemorySize, SMEM_EDGE);

    dim3 gn((NN + 63) / 64, 4);

    coord_diff_kernel<<<(NE + 255) / 256, 256>>>(ei, x, cdp);

    const float* hcur = h0;
    float* houts[2] = {h1, outh};
    for (int l = 0; l < 2; ++l) {
        // node precompute: Pa = h @ ew1[0:256], Pb = h @ ew1[256:512]
        node_gemm<<<gn, 256>>>(hcur, p[l][0], H, nullptr, nullptr, nullptr, nullptr, Pa, NN, 0);
        node_gemm<<<gn, 256>>>(hcur, p[l][0] + 256 * H, H, nullptr, nullptr, nullptr, nullptr, Pb, NN, 0);
        cudaMemsetAsync(agg, 0, (size_t)NN * H * sizeof(float), 0);
        edge_kernel<false><<<NE / 64, 256, SMEM_EDGE>>>(
            ei, ea, Pa, Pb, p[l][0] + 512 * H, p[l][1], p[l][2], p[l][3], p[l][8], p[l][9],
            agg, nullptr);
        // q = silu(h@nw1_top + agg@nw1_bot + nb1)
        node_gemm<<<gn, 256>>>(hcur, p[l][4], H, agg, p[l][4] + 256 * H, p[l][5], nullptr, q, NN, 1);
        // h_next = h + q@nw2 + nb2
        node_gemm<<<gn, 256>>>(q, p[l][6], H, nullptr, nullptr, p[l][7], hcur, houts[l], NN, 0);
        hcur = houts[l];
    }

    // coordinate update
    node_gemm<<<gn, 256>>>(hcur, cw1, H, nullptr, nullptr, nullptr, nullptr, Pa, NN, 0);
    node_gemm<<<gn, 256>>>(hcur, cw1 + 256 * H, H, nullptr, nullptr, nullptr, nullptr, Pb, NN, 0);
    cudaMemsetAsync(aggx, 0, (size_t)NN * 3 * sizeof(float), 0);
    edge_kernel<true><<<NE / 64, 256, SMEM_EDGE>>>(
        ei, ea, Pa, Pb, cw1 + 512 * H, cb1, cw2, cb2, cw3, nullptr, aggx, cdp);
    x_final_kernel<<<(NN * 3 + 255) / 256, 256>>>(x, aggx, outx);
}

// round 3
// speedup vs baseline: 1.8952x; 1.8952x over previous
#include <cuda_runtime.h>
#include <math.h>
#include <stdint.h>

#define NN 10000
#define NE 320000
#define H  256

// ---------------- scratch ----------------
__device__ float g_Pa[NN * H];
__device__ float g_Pb[NN * H];
__device__ float g_agg[NN * H];
__device__ float g_q[NN * H];
__device__ float g_h1[NN * H];
__device__ float g_cd[NE * 3];
__device__ float g_aggx[NN * 3];

__device__ __forceinline__ float sigmf(float v) { return 1.0f / (1.0f + __expf(-v)); }
__device__ __forceinline__ float siluf(float v) { return v / (1.0f + __expf(-v)); }
__device__ __forceinline__ float tf32r(float v) {
    float o; asm("cvt.rna.tf32.f32 %0, %1;" : "=f"(o) : "f"(v)); return o;
}
__device__ __forceinline__ void mma_tf32(float c[4], uint32_t a0, uint32_t a1, uint32_t a2,
                                         uint32_t a3, uint32_t b0, uint32_t b1) {
    asm volatile(
        "mma.sync.aligned.m16n8k8.row.col.f32.tf32.tf32.f32 "
        "{%0,%1,%2,%3}, {%4,%5,%6,%7}, {%8,%9}, {%0,%1,%2,%3};"
        : "+f"(c[0]), "+f"(c[1]), "+f"(c[2]), "+f"(c[3])
        : "r"(a0), "r"(a1), "r"(a2), "r"(a3), "r"(b0), "r"(b1));
}

// smem strides (floats): 260 = 256 + 4 -> conflict-free fragment loads
#define STRD 260
// edge smem layout (float offsets)
#define E_U    0
#define E_B    16640
#define E_PS   24960
#define E_ATT  25024
#define E_B2S  25088
#define E_WVS  25344
#define E_RIDX 25600
#define E_CIDX 25664
#define E_EA   25728
#define E_FLOATS 25856
#define EDGE_SMEM (E_FLOATS * 4)
#define NODE_SMEM (24960 * 4)

// ---- warp-mma inner chunk: acc[16][4] += u_s[r0..r0+15][kbase..+31] @ B_s[0..31][nh..nh+127] ----
__device__ __forceinline__ void warp_mma_chunk(const float* u_s, const float* B_s,
                                               int r0, int nh, int kbase, int lane,
                                               float acc[16][4]) {
    int g = lane >> 2, tig = lane & 3;
#pragma unroll
    for (int ks = 0; ks < 4; ++ks) {
        int k0 = ks * 8;
        const float* ua = u_s + (size_t)(r0 + g) * STRD + kbase + k0 + tig;
        const float* ub = ua + 8 * STRD;
        uint32_t a0 = __float_as_uint(ua[0]);
        uint32_t a1 = __float_as_uint(ub[0]);
        uint32_t a2 = __float_as_uint(ua[4]);
        uint32_t a3 = __float_as_uint(ub[4]);
        const float* b0p = B_s + (size_t)(k0 + tig) * STRD + nh + g;
        const float* b1p = b0p + 4 * STRD;
#pragma unroll
        for (int nt = 0; nt < 16; ++nt) {
            uint32_t b0 = __float_as_uint(b0p[nt * 8]);
            uint32_t b1 = __float_as_uint(b1p[nt * 8]);
            mma_tf32(acc[nt], a0, a1, a2, a3, b0, b1);
        }
    }
}

// ---------------- coord2diff ----------------
__global__ void coord_diff_kernel(const int* __restrict__ ei, const float* __restrict__ x,
                                  float* __restrict__ cd) {
    int e = blockIdx.x * blockDim.x + threadIdx.x;
    if (e >= NE) return;
    int r = ei[e], c = ei[NE + e];
    float dx = x[r * 3 + 0] - x[c * 3 + 0];
    float dy = x[r * 3 + 1] - x[c * 3 + 1];
    float dz = x[r * 3 + 2] - x[c * 3 + 2];
    float rad = dx * dx + dy * dy + dz * dz;
    float inv = 1.0f / (sqrtf(rad + 1e-8f) + 1.0f);
    cd[e * 3 + 0] = dx * inv;
    cd[e * 3 + 1] = dy * inv;
    cd[e * 3 + 2] = dz * inv;
}

// ---------------- node GEMM via warp-mma ----------------
// C[M,256] = [act](A1@B1 [+ A2@B2] + bias) [+ resid];  all K = 256.
__global__ __launch_bounds__(256, 2) void node_mma(
    const float* __restrict__ A1, const float* __restrict__ B1,
    const float* __restrict__ A2, const float* __restrict__ B2,
    const float* __restrict__ bias, const float* __restrict__ resid,
    float* __restrict__ C, int M, int act) {
    extern __shared__ float sm[];
    float* u_s = sm;             // 64 x STRD
    float* B_s = sm + 16640;     // 32 x STRD
    int tid = threadIdx.x, wid = tid >> 5, lane = tid & 31;
    int m0 = blockIdx.x * 64;
    int r0 = (wid >> 1) * 16, nh = (wid & 1) * 128;

    float acc[16][4] = {};
    int npass = A2 ? 2 : 1;
    for (int pass = 0; pass < npass; ++pass) {
        const float* A = pass ? A2 : A1;
        const float* B = pass ? B2 : B1;
        __syncthreads();
#pragma unroll 4
        for (int it = 0; it < 16; ++it) {
            int idx = it * 256 + tid;
            int e = idx >> 6;
            int kq = (idx & 63) << 2;
            int row = min(m0 + e, M - 1);
            float4 v = *(const float4*)&A[(size_t)row * H + kq];
            v.x = tf32r(v.x); v.y = tf32r(v.y); v.z = tf32r(v.z); v.w = tf32r(v.w);
            *(float4*)&u_s[e * STRD + kq] = v;
        }
        for (int kc = 0; kc < 8; ++kc) {
            __syncthreads();
#pragma unroll 4
            for (int i = 0; i < 8; ++i) {
                int idx = i * 256 + tid;
                int kr = idx >> 6;
                int c4 = (idx & 63) << 2;
                float4 v = *(const float4*)&B[(size_t)(kc * 32 + kr) * H + c4];
                v.x = tf32r(v.x); v.y = tf32r(v.y); v.z = tf32r(v.z); v.w = tf32r(v.w);
                *(float4*)&B_s[kr * STRD + c4] = v;
            }
            __syncthreads();
            warp_mma_chunk(u_s, B_s, r0, nh, kc * 32, lane, acc);
        }
    }
    // --- epilogue ---
    int g = lane >> 2, tig = lane & 3;
    int row0 = m0 + r0 + g, row1 = row0 + 8;
#pragma unroll
    for (int nt = 0; nt < 16; ++nt) {
        int col = nh + nt * 8 + 2 * tig;
        float b0v = 0.f, b1v = 0.f;
        if (bias) { b0v = bias[col]; b1v = bias[col + 1]; }
        float v00 = acc[nt][0] + b0v, v01 = acc[nt][1] + b1v;
        float v10 = acc[nt][2] + b0v, v11 = acc[nt][3] + b1v;
        if (act) { v00 = siluf(v00); v01 = siluf(v01); v10 = siluf(v10); v11 = siluf(v11); }
        if (row0 < M) {
            if (resid) {
                float2 rv = *(const float2*)&resid[(size_t)row0 * H + col];
                v00 += rv.x; v01 += rv.y;
            }
            *(float2*)&C[(size_t)row0 * H + col] = make_float2(v00, v01);
        }
        if (row1 < M) {
            if (resid) {
                float2 rv = *(const float2*)&resid[(size_t)row1 * H + col];
                v10 += rv.x; v11 += rv.y;
            }
            *(float2*)&C[(size_t)row1 * H + col] = make_float2(v10, v11);
        }
    }
}

// ---------------- fused edge kernel, warp-mma tf32 ----------------
template <bool COORD>
__global__ __launch_bounds__(256, 2) void edge_mma_kernel(
    const int* __restrict__ ei, const float* __restrict__ eattr,
    const float* __restrict__ Pa, const float* __restrict__ Pb,
    const float* __restrict__ wtail, const float* __restrict__ b1,
    const float* __restrict__ W2, const float* __restrict__ b2,
    const float* __restrict__ wv, const float* __restrict__ ab,
    float* __restrict__ agg, const float* __restrict__ cd) {
    extern __shared__ float sm[];
    float* u_s = sm + E_U;
    float* B_s = sm + E_B;
    float* ps  = sm + E_PS;
    float* att = sm + E_ATT;
    float* b2s = sm + E_B2S;
    float* wvs = sm + E_WVS;
    int* ridx  = (int*)(sm + E_RIDX);
    int* cidx  = (int*)(sm + E_CIDX);
    float* eas = sm + E_EA;

    int tid = threadIdx.x, wid = tid >> 5, lane = tid & 31;
    int e0 = blockIdx.x * 64;
    int r0 = (wid >> 1) * 16, nh = (wid & 1) * 128;

    if (tid < 64) {
        ridx[tid] = ei[e0 + tid];
        cidx[tid] = ei[NE + e0 + tid];
        float2 a = ((const float2*)eattr)[e0 + tid];
        eas[tid] = a.x;
        eas[64 + tid] = a.y;
        ps[tid] = 0.f;
    }
    b2s[tid] = b2[tid];
    wvs[tid] = wv[tid];
    __syncthreads();

    // phase A: u = silu(Pa[row]+Pb[col]+ea@wtail+b1), tf32-rounded, into u_s
#pragma unroll 4
    for (int it = 0; it < 16; ++it) {
        int idx = it * 256 + tid;
        int e = idx >> 6;
        int kq = (idx & 63) << 2;
        int r = ridx[e], cl = cidx[e];
        float4 pa = *(const float4*)&Pa[(size_t)r * H + kq];
        float4 pb = *(const float4*)&Pb[(size_t)cl * H + kq];
        float4 w0 = *(const float4*)&wtail[kq];
        float4 w1 = *(const float4*)&wtail[H + kq];
        float4 bv = *(const float4*)&b1[kq];
        float a0 = eas[e], a1 = eas[64 + e];
        float4 t;
        t.x = tf32r(siluf(pa.x + pb.x + a0 * w0.x + a1 * w1.x + bv.x));
        t.y = tf32r(siluf(pa.y + pb.y + a0 * w0.y + a1 * w1.y + bv.y));
        t.z = tf32r(siluf(pa.z + pb.z + a0 * w0.z + a1 * w1.z + bv.z));
        t.w = tf32r(siluf(pa.w + pb.w + a0 * w0.w + a1 * w1.w + bv.w));
        *(float4*)&u_s[e * STRD + kq] = t;
    }

    float acc[16][4] = {};
    for (int kc = 0; kc < 8; ++kc) {
        __syncthreads();
#pragma unroll 4
        for (int i = 0; i < 8; ++i) {
            int idx = i * 256 + tid;
            int kr = idx >> 6;
            int c4 = (idx & 63) << 2;
            float4 v = *(const float4*)&W2[(size_t)(kc * 32 + kr) * H + c4];
            v.x = tf32r(v.x); v.y = tf32r(v.y); v.z = tf32r(v.z); v.w = tf32r(v.w);
            *(float4*)&B_s[kr * STRD + c4] = v;
        }
        __syncthreads();
        warp_mma_chunk(u_s, B_s, r0, nh, kc * 32, lane, acc);
    }
    __syncthreads();  // all mma reads of u_s done before mij overwrites it

    // epilogue: silu + attention/phi dot
    int g = lane >> 2, tig = lane & 3;
    int row0 = r0 + g, row1 = row0 + 8;
    float p0 = 0.f, p1 = 0.f;
#pragma unroll
    for (int nt = 0; nt < 16; ++nt) {
        int col = nh + nt * 8 + 2 * tig;
        float bb0 = b2s[col], bb1 = b2s[col + 1];
        float w0 = wvs[col], w1 = wvs[col + 1];
        float v00 = siluf(acc[nt][0] + bb0), v01 = siluf(acc[nt][1] + bb1);
        float v10 = siluf(acc[nt][2] + bb0), v11 = siluf(acc[nt][3] + bb1);
        if (!COORD) {
            *(float2*)&u_s[row0 * STRD + col] = make_float2(v00, v01);
            *(float2*)&u_s[row1 * STRD + col] = make_float2(v10, v11);
        }
        p0 += v00 * w0 + v01 * w1;
        p1 += v10 * w0 + v11 * w1;
    }
    atomicAdd(&ps[row0], p0);
    atomicAdd(&ps[row1], p1);
    __syncthreads();

    if (COORD) {
        if (tid < 64) {
            float phi = ps[tid] * 0.01f;
            int r = ridx[tid];
            const float* c = cd + (size_t)(e0 + tid) * 3;
            atomicAdd(&agg[(size_t)r * 3 + 0], c[0] * phi);
            atomicAdd(&agg[(size_t)r * 3 + 1], c[1] * phi);
            atomicAdd(&agg[(size_t)r * 3 + 2], c[2] * phi);
        }
    } else {
        if (tid < 64) att[tid] = sigmf(ps[tid] + ab[0]) * 0.01f;
        __syncthreads();
        int row = tid >> 2;
        int c0 = (tid & 3) << 6;
        float a = att[row];
        int r = ridx[row];
        float* dst = agg + (size_t)r * H + c0;
        const float* src = u_s + row * STRD + c0;
#pragma unroll
        for (int j = 0; j < 16; ++j) {
            float4 v = *(const float4*)&src[4 * j];
            atomicAdd(dst + 4 * j + 0, v.x * a);
            atomicAdd(dst + 4 * j + 1, v.y * a);
            atomicAdd(dst + 4 * j + 2, v.z * a);
            atomicAdd(dst + 4 * j + 3, v.w * a);
        }
    }
}

__global__ void x_final_kernel(const float* __restrict__ x, const float* __restrict__ aggx,
                               float* __restrict__ out) {
    int i = blockIdx.x * blockDim.x + threadIdx.x;
    if (i < NN * 3) out[i] = x[i] + aggx[i];
}

// ---------------- launch ----------------
extern "C" void kernel_launch(void* const* d_in, const int* in_sizes, int n_in,
                              void* d_out, int out_size) {
    const float* h0 = (const float*)d_in[0];
    const float* x = (const float*)d_in[1];
    const int* ei = (const int*)d_in[2];
    const float* ea = (const float*)d_in[3];
    const float* p[2][10];
    for (int l = 0; l < 2; ++l)
        for (int i = 0; i < 10; ++i) p[l][i] = (const float*)d_in[4 + l * 10 + i];
    // p[l]: 0 ew1, 1 eb1, 2 ew2, 3 eb2, 4 nw1, 5 nb1, 6 nw2, 7 nb2, 8 aw, 9 ab
    const float* cw1 = (const float*)d_in[24];
    const float* cb1 = (const float*)d_in[25];
    const float* cw2 = (const float*)d_in[26];
    const float* cb2 = (const float*)d_in[27];
    const float* cw3 = (const float*)d_in[28];

    float* outh = (float*)d_out;
    float* outx = outh + (size_t)NN * H;

    float *Pa, *Pb, *agg, *q, *h1, *cdp, *aggx;
    cudaGetSymbolAddress((void**)&Pa, g_Pa);
    cudaGetSymbolAddress((void**)&Pb, g_Pb);
    cudaGetSymbolAddress((void**)&agg, g_agg);
    cudaGetSymbolAddress((void**)&q, g_q);
    cudaGetSymbolAddress((void**)&h1, g_h1);
    cudaGetSymbolAddress((void**)&cdp, g_cd);
    cudaGetSymbolAddress((void**)&aggx, g_aggx);

    cudaFuncSetAttribute(edge_mma_kernel<false>, cudaFuncAttributeMaxDynamicSharedMemorySize, EDGE_SMEM);
    cudaFuncSetAttribute(edge_mma_kernel<true>, cudaFuncAttributeMaxDynamicSharedMemorySize, EDGE_SMEM);
    cudaFuncSetAttribute(node_mma, cudaFuncAttributeMaxDynamicSharedMemorySize, NODE_SMEM);

    int gnode = (NN + 63) / 64;

    coord_diff_kernel<<<(NE + 255) / 256, 256>>>(ei, x, cdp);

    const float* hcur = h0;
    float* houts[2] = {h1, outh};
    for (int l = 0; l < 2; ++l) {
        node_mma<<<gnode, 256, NODE_SMEM>>>(hcur, p[l][0], nullptr, nullptr,
                                            nullptr, nullptr, Pa, NN, 0);
        node_mma<<<gnode, 256, NODE_SMEM>>>(hcur, p[l][0] + 256 * H, nullptr, nullptr,
                                            nullptr, nullptr, Pb, NN, 0);
        cudaMemsetAsync(agg, 0, (size_t)NN * H * sizeof(float), 0);
        edge_mma_kernel<false><<<NE / 64, 256, EDGE_SMEM>>>(
            ei, ea, Pa, Pb, p[l][0] + 512 * H, p[l][1], p[l][2], p[l][3], p[l][8], p[l][9],
            agg, nullptr);
        node_mma<<<gnode, 256, NODE_SMEM>>>(hcur, p[l][4], agg, p[l][4] + 256 * H,
                                            p[l][5], nullptr, q, NN, 1);
        node_mma<<<gnode, 256, NODE_SMEM>>>(q, p[l][6], nullptr, nullptr,
                                            p[l][7], hcur, houts[l], NN, 0);
        hcur = houts[l];
    }

    node_mma<<<gnode, 256, NODE_SMEM>>>(hcur, cw1, nullptr, nullptr,
                                        nullptr, nullptr, Pa, NN, 0);
    node_mma<<<gnode, 256, NODE_SMEM>>>(hcur, cw1 + 256 * H, nullptr, nullptr,
                                        nullptr, nullptr, Pb, NN, 0);
    cudaMemsetAsync(aggx, 0, (size_t)NN * 3 * sizeof(float), 0);
    edge_mma_kernel<true><<<NE / 64, 256, EDGE_SMEM>>>(
        ei, ea, Pa, Pb, cw1 + 512 * H, cb1, cw2, cb2, cw3, nullptr, aggx, cdp);
    x_final_kernel<<<(NN * 3 + 255) / 256, 256>>>(x, aggx, outx);
}

// round 4
// speedup vs baseline: 3.5718x; 1.8846x over previous
#include <cuda_runtime.h>
#include <cuda_bf16.h>
#include <math.h>
#include <stdint.h>

#define NN 10000
#define NE 320000
#define H  256

// ---------------- scratch ----------------
__device__ float g_Pa[NN * H];
__device__ float g_Pb[NN * H];
__device__ float g_agg[NN * H];
__device__ float g_q[NN * H];
__device__ float g_h1[NN * H];
__device__ float g_aggx[NN * 3];
__device__ int   g_deg[NN];
__device__ int   g_cur[NN];
__device__ int   g_srow[NE];
__device__ int   g_scol[NE];
__device__ float2 g_sea[NE];
__device__ unsigned g_W2F[3 * 32768];   // fragment-ordered bf16-pair W2 (3 instances)

__device__ __forceinline__ float sigmf(float v) { return 1.0f / (1.0f + __expf(-v)); }
__device__ __forceinline__ float siluf(float v) { return v / (1.0f + __expf(-v)); }
__device__ __forceinline__ float tf32r(float v) {
    float o; asm("cvt.rna.tf32.f32 %0, %1;" : "=f"(o) : "f"(v)); return o;
}
__device__ __forceinline__ uint32_t pack2(float x, float y) {
    __nv_bfloat162 t = __floats2bfloat162_rn(x, y);
    return *(uint32_t*)&t;
}
__device__ __forceinline__ float2 up2(uint32_t v) {
    return __bfloat1622float2(*(__nv_bfloat162*)&v);
}
__device__ __forceinline__ void mma_bf16(float c[4], uint32_t a0, uint32_t a1, uint32_t a2,
                                         uint32_t a3, uint32_t b0, uint32_t b1) {
    asm volatile(
        "mma.sync.aligned.m16n8k16.row.col.f32.bf16.bf16.f32 "
        "{%0,%1,%2,%3}, {%4,%5,%6,%7}, {%8,%9}, {%0,%1,%2,%3};"
        : "+f"(c[0]), "+f"(c[1]), "+f"(c[2]), "+f"(c[3])
        : "r"(a0), "r"(a1), "r"(a2), "r"(a3), "r"(b0), "r"(b1));
}
__device__ __forceinline__ void mma_tf32(float c[4], uint32_t a0, uint32_t a1, uint32_t a2,
                                         uint32_t a3, uint32_t b0, uint32_t b1) {
    asm volatile(
        "mma.sync.aligned.m16n8k8.row.col.f32.tf32.tf32.f32 "
        "{%0,%1,%2,%3}, {%4,%5,%6,%7}, {%8,%9}, {%0,%1,%2,%3};"
        : "+f"(c[0]), "+f"(c[1]), "+f"(c[2]), "+f"(c[3])
        : "r"(a0), "r"(a1), "r"(a2), "r"(a3), "r"(b0), "r"(b1));
}

// ================= prep kernels =================
__global__ void hist_kernel(const int* __restrict__ ei) {
    int e = blockIdx.x * 256 + threadIdx.x;
    if (e < NE) atomicAdd(&g_deg[ei[e]], 1);
}
__global__ void scan_kernel() {
    __shared__ int part[256];
    int t = threadIdx.x;
    int base = t * 40;
    int s = 0;
    for (int j = 0; j < 40; ++j) {
        int i = base + j;
        if (i < NN) s += g_deg[i];
    }
    part[t] = s;
    __syncthreads();
    if (t == 0) {
        int run = 0;
        for (int i = 0; i < 256; ++i) { int v = part[i]; part[i] = run; run += v; }
    }
    __syncthreads();
    int run = part[t];
    for (int j = 0; j < 40; ++j) {
        int i = base + j;
        if (i < NN) { g_cur[i] = run; run += g_deg[i]; }
    }
}
__global__ void scatter_kernel(const int* __restrict__ ei, const float* __restrict__ ea) {
    int e = blockIdx.x * 256 + threadIdx.x;
    if (e >= NE) return;
    int r = ei[e];
    int pos = atomicAdd(&g_cur[r], 1);
    g_srow[pos] = r;
    g_scol[pos] = ei[NE + e];
    g_sea[pos] = ((const float2*)ea)[e];
}
// fragment-ordered W2 -> bf16 pairs.
// idx i: r=i&1, lane=(i>>1)&31, nt=(i>>6)&31, ks=(i>>11)&1, kc=i>>12
// g=lane>>2, tig=lane&3; k = kc*32+ks*16+2*tig+8*r; n = nt*8+g
__global__ void wfprep_kernel(const float* __restrict__ W, unsigned* __restrict__ out) {
    int i = blockIdx.x * 256 + threadIdx.x;   // 32768 total
    int r = i & 1, lane = (i >> 1) & 31, nt = (i >> 6) & 31, ks = (i >> 11) & 1, kc = i >> 12;
    int g = lane >> 2, tig = lane & 3;
    int k = kc * 32 + ks * 16 + 2 * tig + 8 * r;
    int n = nt * 8 + g;
    out[i] = pack2(W[k * H + n], W[(k + 1) * H + n]);
}

// ================= node GEMM via warp-mma tf32 (unchanged from R3) =================
#define STRD 260
#define NODE_SMEM (24960 * 4)
__device__ __forceinline__ void warp_mma_chunk(const float* u_s, const float* B_s,
                                               int r0, int nh, int kbase, int lane,
                                               float acc[16][4]) {
    int g = lane >> 2, tig = lane & 3;
#pragma unroll
    for (int ks = 0; ks < 4; ++ks) {
        int k0 = ks * 8;
        const float* ua = u_s + (size_t)(r0 + g) * STRD + kbase + k0 + tig;
        const float* ub = ua + 8 * STRD;
        uint32_t a0 = __float_as_uint(ua[0]);
        uint32_t a1 = __float_as_uint(ub[0]);
        uint32_t a2 = __float_as_uint(ua[4]);
        uint32_t a3 = __float_as_uint(ub[4]);
        const float* b0p = B_s + (size_t)(k0 + tig) * STRD + nh + g;
        const float* b1p = b0p + 4 * STRD;
#pragma unroll
        for (int nt = 0; nt < 16; ++nt) {
            uint32_t b0 = __float_as_uint(b0p[nt * 8]);
            uint32_t b1 = __float_as_uint(b1p[nt * 8]);
            mma_tf32(acc[nt], a0, a1, a2, a3, b0, b1);
        }
    }
}
__global__ __launch_bounds__(256, 2) void node_mma(
    const float* __restrict__ A1, const float* __restrict__ B1,
    const float* __restrict__ A2, const float* __restrict__ B2,
    const float* __restrict__ bias, const float* __restrict__ resid,
    float* __restrict__ C, int M, int act) {
    extern __shared__ float sm[];
    float* u_s = sm;
    float* B_s = sm + 16640;
    int tid = threadIdx.x, wid = tid >> 5, lane = tid & 31;
    int m0 = blockIdx.x * 64;
    int r0 = (wid >> 1) * 16, nh = (wid & 1) * 128;

    float acc[16][4] = {};
    int npass = A2 ? 2 : 1;
    for (int pass = 0; pass < npass; ++pass) {
        const float* A = pass ? A2 : A1;
        const float* B = pass ? B2 : B1;
        __syncthreads();
#pragma unroll 4
        for (int it = 0; it < 16; ++it) {
            int idx = it * 256 + tid;
            int e = idx >> 6;
            int kq = (idx & 63) << 2;
            int row = min(m0 + e, M - 1);
            float4 v = *(const float4*)&A[(size_t)row * H + kq];
            v.x = tf32r(v.x); v.y = tf32r(v.y); v.z = tf32r(v.z); v.w = tf32r(v.w);
            *(float4*)&u_s[e * STRD + kq] = v;
        }
        for (int kc = 0; kc < 8; ++kc) {
            __syncthreads();
#pragma unroll 4
            for (int i = 0; i < 8; ++i) {
                int idx = i * 256 + tid;
                int kr = idx >> 6;
                int c4 = (idx & 63) << 2;
                float4 v = *(const float4*)&B[(size_t)(kc * 32 + kr) * H + c4];
                v.x = tf32r(v.x); v.y = tf32r(v.y); v.z = tf32r(v.z); v.w = tf32r(v.w);
                *(float4*)&B_s[kr * STRD + c4] = v;
            }
            __syncthreads();
            warp_mma_chunk(u_s, B_s, r0, nh, kc * 32, lane, acc);
        }
    }
    int g = lane >> 2, tig = lane & 3;
    int row0 = m0 + r0 + g, row1 = row0 + 8;
#pragma unroll
    for (int nt = 0; nt < 16; ++nt) {
        int col = nh + nt * 8 + 2 * tig;
        float b0v = 0.f, b1v = 0.f;
        if (bias) { b0v = bias[col]; b1v = bias[col + 1]; }
        float v00 = acc[nt][0] + b0v, v01 = acc[nt][1] + b1v;
        float v10 = acc[nt][2] + b0v, v11 = acc[nt][3] + b1v;
        if (act) { v00 = siluf(v00); v01 = siluf(v01); v10 = siluf(v10); v11 = siluf(v11); }
        if (row0 < M) {
            if (resid) {
                float2 rv = *(const float2*)&resid[(size_t)row0 * H + col];
                v00 += rv.x; v01 += rv.y;
            }
            *(float2*)&C[(size_t)row0 * H + col] = make_float2(v00, v01);
        }
        if (row1 < M) {
            if (resid) {
                float2 rv = *(const float2*)&resid[(size_t)row1 * H + col];
                v10 += rv.x; v11 += rv.y;
            }
            *(float2*)&C[(size_t)row1 * H + col] = make_float2(v10, v11);
        }
    }
}

// ================= edge kernel: bf16 mma + sorted-row segmented epilogue =================
// smem (u32 units)
#define EU   0        // u tile: 64 rows x 132 u32-words (264 bf16, stride word%32==4 -> conflict-free)
#define EB   8448     // B fragments for one 32-k chunk: 4096 u32
#define EPS  12544    // float ps[64]
#define EATT 12608    // float att[64]
#define EB2  12672    // float b2s[256]
#define EWV  12928    // float wvs[256]
#define ESR  13184    // int srow[64]
#define ESC  13248    // int scol[64]
#define EEA  13312    // float eas[128]
#define ETOT 13440
#define EDGE_SMEM (ETOT * 4)

template <bool COORD>
__global__ __launch_bounds__(256, 2) void edge_bf16_kernel(
    const float* __restrict__ Pa, const float* __restrict__ Pb,
    const float* __restrict__ wtail, const float* __restrict__ b1,
    const unsigned* __restrict__ W2F, const float* __restrict__ b2,
    const float* __restrict__ wv, const float* __restrict__ ab,
    float* __restrict__ agg, const float* __restrict__ xg) {
    extern __shared__ uint32_t sm32[];
    float* ps   = (float*)(sm32 + EPS);
    float* att_s = (float*)(sm32 + EATT);
    float* b2s  = (float*)(sm32 + EB2);
    float* wvs  = (float*)(sm32 + EWV);
    int* srow_s = (int*)(sm32 + ESR);
    int* scol_s = (int*)(sm32 + ESC);
    float* eas  = (float*)(sm32 + EEA);

    int tid = threadIdx.x, wid = tid >> 5, lane = tid & 31;
    int g = lane >> 2, tig = lane & 3;
    int e0 = blockIdx.x * 64;
    int r0 = (wid >> 1) * 16, ntb = (wid & 1) * 16;

    if (tid < 64) {
        srow_s[tid] = g_srow[e0 + tid];
        scol_s[tid] = g_scol[e0 + tid];
        float2 a = g_sea[e0 + tid];
        eas[tid] = a.x;
        eas[64 + tid] = a.y;
        ps[tid] = 0.f;
    }
    b2s[tid] = b2[tid];
    wvs[tid] = wv[tid];
    __syncthreads();

    // phase A: u = silu(Pa[row]+Pb[col]+ea@wtail+b1) -> bf16 pairs in u_s
#pragma unroll 4
    for (int it = 0; it < 16; ++it) {
        int idx = it * 256 + tid;
        int e = idx >> 6;
        int kq = (idx & 63) << 2;
        int r = srow_s[e], cl = scol_s[e];
        float4 pa = *(const float4*)&Pa[(size_t)r * H + kq];
        float4 pb = *(const float4*)&Pb[(size_t)cl * H + kq];
        float4 w0 = *(const float4*)&wtail[kq];
        float4 w1 = *(const float4*)&wtail[H + kq];
        float4 bv = *(const float4*)&b1[kq];
        float a0 = eas[e], a1 = eas[64 + e];
        float t0 = siluf(pa.x + pb.x + a0 * w0.x + a1 * w1.x + bv.x);
        float t1 = siluf(pa.y + pb.y + a0 * w0.y + a1 * w1.y + bv.y);
        float t2 = siluf(pa.z + pb.z + a0 * w0.z + a1 * w1.z + bv.z);
        float t3 = siluf(pa.w + pb.w + a0 * w0.w + a1 * w1.w + bv.w);
        uint2 w;
        w.x = pack2(t0, t1);
        w.y = pack2(t2, t3);
        *(uint2*)&sm32[EU + e * 132 + (kq >> 1)] = w;
    }

    // MMA: D[64,256] = u @ W2, K streamed in 8 chunks of 32
    float acc[16][4] = {};
    for (int kc = 0; kc < 8; ++kc) {
        __syncthreads();
        const uint4* src = (const uint4*)(W2F + kc * 4096);
        uint4* dstB = (uint4*)(sm32 + EB);
#pragma unroll
        for (int i = 0; i < 4; ++i) dstB[i * 256 + tid] = src[i * 256 + tid];
        __syncthreads();
#pragma unroll
        for (int ks = 0; ks < 2; ++ks) {
            int kw = kc * 16 + ks * 8;
            const uint32_t* ua = sm32 + EU + (r0 + g) * 132 + kw + tig;
            uint32_t a0 = ua[0], a1 = ua[8 * 132], a2 = ua[4], a3 = ua[8 * 132 + 4];
            const uint32_t* bp = sm32 + EB + ((ks * 32 + ntb) * 32 + lane) * 2;
#pragma unroll
            for (int nt = 0; nt < 16; ++nt) {
                uint2 b = *(const uint2*)(bp + nt * 64);
                mma_bf16(acc[nt], a0, a1, a2, a3, b.x, b.y);
            }
        }
    }
    __syncthreads();   // mma reads of u_s done before mij overwrites it

    // epilogue: silu + dot(wv)
    int row0 = r0 + g, row1 = row0 + 8;
    float p0 = 0.f, p1 = 0.f;
#pragma unroll
    for (int nt = 0; nt < 16; ++nt) {
        int col = (ntb + nt) * 8 + 2 * tig;
        float bb0 = b2s[col], bb1 = b2s[col + 1];
        float w0 = wvs[col], w1 = wvs[col + 1];
        float v00 = siluf(acc[nt][0] + bb0), v01 = siluf(acc[nt][1] + bb1);
        float v10 = siluf(acc[nt][2] + bb0), v11 = siluf(acc[nt][3] + bb1);
        if (!COORD) {
            sm32[EU + row0 * 132 + (ntb + nt) * 4 + tig] = pack2(v00, v01);
            sm32[EU + row1 * 132 + (ntb + nt) * 4 + tig] = pack2(v10, v11);
        }
        p0 += v00 * w0 + v01 * w1;
        p1 += v10 * w0 + v11 * w1;
    }
    atomicAdd(&ps[row0], p0);
    atomicAdd(&ps[row1], p1);
    __syncthreads();

    if (COORD) {
        if (tid < 64) {
            float phi = ps[tid] * 0.01f;
            int r = srow_s[tid], c = scol_s[tid];
            float dx = xg[r * 3 + 0] - xg[c * 3 + 0];
            float dy = xg[r * 3 + 1] - xg[c * 3 + 1];
            float dz = xg[r * 3 + 2] - xg[c * 3 + 2];
            float inv = 1.0f / (sqrtf(dx * dx + dy * dy + dz * dz + 1e-8f) + 1.0f);
            atomicAdd(&agg[(size_t)r * 3 + 0], dx * inv * phi);
            atomicAdd(&agg[(size_t)r * 3 + 1], dy * inv * phi);
            atomicAdd(&agg[(size_t)r * 3 + 2], dz * inv * phi);
        }
    } else {
        if (tid < 64) att_s[tid] = sigmf(ps[tid] + ab[0]) * 0.01f;
        __syncthreads();
        // segmented reduction over sorted rows: 8 slot-groups x 32 col-chunks of 8
        int cch = tid & 31;
        int s0 = (tid >> 5) * 8;
        float av[8] = {};
        int currow = srow_s[s0];
        for (int s = s0; s < s0 + 8; ++s) {
            int r = srow_s[s];
            if (r != currow) {
                float* dst = agg + (size_t)currow * H + cch * 8;
#pragma unroll
                for (int j = 0; j < 8; ++j) { atomicAdd(dst + j, av[j]); av[j] = 0.f; }
                currow = r;
            }
            float a = att_s[s];
            uint4 w4 = *(const uint4*)(sm32 + EU + s * 132 + cch * 4);
            float2 f;
            f = up2(w4.x); av[0] += f.x * a; av[1] += f.y * a;
            f = up2(w4.y); av[2] += f.x * a; av[3] += f.y * a;
            f = up2(w4.z); av[4] += f.x * a; av[5] += f.y * a;
            f = up2(w4.w); av[6] += f.x * a; av[7] += f.y * a;
        }
        float* dst = agg + (size_t)currow * H + cch * 8;
#pragma unroll
        for (int j = 0; j < 8; ++j) atomicAdd(dst + j, av[j]);
    }
}

__global__ void x_final_kernel(const float* __restrict__ x, const float* __restrict__ aggx,
                               float* __restrict__ out) {
    int i = blockIdx.x * blockDim.x + threadIdx.x;
    if (i < NN * 3) out[i] = x[i] + aggx[i];
}

// ================= launch =================
extern "C" void kernel_launch(void* const* d_in, const int* in_sizes, int n_in,
                              void* d_out, int out_size) {
    const float* h0 = (const float*)d_in[0];
    const float* x = (const float*)d_in[1];
    const int* ei = (const int*)d_in[2];
    const float* ea = (const float*)d_in[3];
    const float* p[2][10];
    for (int l = 0; l < 2; ++l)
        for (int i = 0; i < 10; ++i) p[l][i] = (const float*)d_in[4 + l * 10 + i];
    // p[l]: 0 ew1, 1 eb1, 2 ew2, 3 eb2, 4 nw1, 5 nb1, 6 nw2, 7 nb2, 8 aw, 9 ab
    const float* cw1 = (const float*)d_in[24];
    const float* cb1 = (const float*)d_in[25];
    const float* cw2 = (const float*)d_in[26];
    const float* cb2 = (const float*)d_in[27];
    const float* cw3 = (const float*)d_in[28];

    float* outh = (float*)d_out;
    float* outx = outh + (size_t)NN * H;

    float *Pa, *Pb, *agg, *q, *h1, *aggx;
    int* deg;
    unsigned* w2f;
    cudaGetSymbolAddress((void**)&Pa, g_Pa);
    cudaGetSymbolAddress((void**)&Pb, g_Pb);
    cudaGetSymbolAddress((void**)&agg, g_agg);
    cudaGetSymbolAddress((void**)&q, g_q);
    cudaGetSymbolAddress((void**)&h1, g_h1);
    cudaGetSymbolAddress((void**)&aggx, g_aggx);
    cudaGetSymbolAddress((void**)&deg, g_deg);
    cudaGetSymbolAddress((void**)&w2f, g_W2F);

    cudaFuncSetAttribute(edge_bf16_kernel<false>, cudaFuncAttributeMaxDynamicSharedMemorySize, EDGE_SMEM);
    cudaFuncSetAttribute(edge_bf16_kernel<true>, cudaFuncAttributeMaxDynamicSharedMemorySize, EDGE_SMEM);
    cudaFuncSetAttribute(node_mma, cudaFuncAttributeMaxDynamicSharedMemorySize, NODE_SMEM);

    int gnode = (NN + 63) / 64;

    // prep: edge counting-sort + fragment-ordered W2
    cudaMemsetAsync(deg, 0, NN * sizeof(int), 0);
    hist_kernel<<<(NE + 255) / 256, 256>>>(ei);
    scan_kernel<<<1, 256>>>();
    scatter_kernel<<<(NE + 255) / 256, 256>>>(ei, ea);
    wfprep_kernel<<<128, 256>>>(p[0][2], w2f + 0 * 32768);
    wfprep_kernel<<<128, 256>>>(p[1][2], w2f + 1 * 32768);
    wfprep_kernel<<<128, 256>>>(cw2, w2f + 2 * 32768);

    const float* hcur = h0;
    float* houts[2] = {h1, outh};
    for (int l = 0; l < 2; ++l) {
        node_mma<<<gnode, 256, NODE_SMEM>>>(hcur, p[l][0], nullptr, nullptr,
                                            nullptr, nullptr, Pa, NN, 0);
        node_mma<<<gnode, 256, NODE_SMEM>>>(hcur, p[l][0] + 256 * H, nullptr, nullptr,
                                            nullptr, nullptr, Pb, NN, 0);
        cudaMemsetAsync(agg, 0, (size_t)NN * H * sizeof(float), 0);
        edge_bf16_kernel<false><<<NE / 64, 256, EDGE_SMEM>>>(
            Pa, Pb, p[l][0] + 512 * H, p[l][1], w2f + l * 32768, p[l][3], p[l][8], p[l][9],
            agg, nullptr);
        node_mma<<<gnode, 256, NODE_SMEM>>>(hcur, p[l][4], agg, p[l][4] + 256 * H,
                                            p[l][5], nullptr, q, NN, 1);
        node_mma<<<gnode, 256, NODE_SMEM>>>(q, p[l][6], nullptr, nullptr,
                                            p[l][7], hcur, houts[l], NN, 0);
        hcur = houts[l];
    }

    node_mma<<<gnode, 256, NODE_SMEM>>>(hcur, cw1, nullptr, nullptr,
                                        nullptr, nullptr, Pa, NN, 0);
    node_mma<<<gnode, 256, NODE_SMEM>>>(hcur, cw1 + 256 * H, nullptr, nullptr,
                                        nullptr, nullptr, Pb, NN, 0);
    cudaMemsetAsync(aggx, 0, (size_t)NN * 3 * sizeof(float), 0);
    edge_bf16_kernel<true><<<NE / 64, 256, EDGE_SMEM>>>(
        Pa, Pb, cw1 + 512 * H, cb1, w2f + 2 * 32768, cb2, cw3, nullptr, aggx, x);
    x_final_kernel<<<(NN * 3 + 255) / 256, 256>>>(x, aggx, outx);
}

// round 5
// speedup vs baseline: 4.4518x; 1.2464x over previous
#include <cuda_runtime.h>
#include <cuda_bf16.h>
#include <math.h>
#include <stdint.h>

#define NN 10000
#define NE 320000
#define H  256

// ---------------- scratch ----------------
__device__ float g_Pa[NN * H];
__device__ float g_Pb[NN * H];
__device__ float g_agg[NN * H];
__device__ float g_q[NN * H];
__device__ float g_h1[NN * H];
__device__ float g_aggx[NN * 3];
__device__ int   g_deg[NN];
__device__ int   g_cur[NN];
__device__ int   g_srow[NE];
__device__ int   g_scol[NE];
__device__ float2 g_sea[NE];
__device__ unsigned g_WF[15 * 32768];   // fragment-ordered bf16-pair weights (15 matrices)

__device__ __forceinline__ float sigmf(float v) { return 1.0f / (1.0f + __expf(-v)); }
__device__ __forceinline__ float siluf(float v) { return v / (1.0f + __expf(-v)); }
__device__ __forceinline__ uint32_t pack2(float x, float y) {
    __nv_bfloat162 t = __floats2bfloat162_rn(x, y);
    return *(uint32_t*)&t;
}
__device__ __forceinline__ float2 up2(uint32_t v) {
    return __bfloat1622float2(*(__nv_bfloat162*)&v);
}
__device__ __forceinline__ void mma_bf16(float c[4], uint32_t a0, uint32_t a1, uint32_t a2,
                                         uint32_t a3, uint32_t b0, uint32_t b1) {
    asm volatile(
        "mma.sync.aligned.m16n8k16.row.col.f32.bf16.bf16.f32 "
        "{%0,%1,%2,%3}, {%4,%5,%6,%7}, {%8,%9}, {%0,%1,%2,%3};"
        : "+f"(c[0]), "+f"(c[1]), "+f"(c[2]), "+f"(c[3])
        : "r"(a0), "r"(a1), "r"(a2), "r"(a3), "r"(b0), "r"(b1));
}

// ---- shared mma core: acc += u_s(rows r0..r0+15, bf16-pair, stride 132 words) @ Bf(direct gmem) ----
__device__ __forceinline__ void mma_block_direct(const uint32_t* u_s, const uint2* __restrict__ Bf,
                                                 int r0, int ntb, int lane, float acc[16][4]) {
    int g = lane >> 2, tig = lane & 3;
    const uint32_t* ua0 = u_s + (r0 + g) * 132 + tig;
#pragma unroll
    for (int kstep = 0; kstep < 16; ++kstep) {
        uint32_t a0 = ua0[kstep * 8];
        uint32_t a1 = ua0[kstep * 8 + 8 * 132];
        uint32_t a2 = ua0[kstep * 8 + 4];
        uint32_t a3 = ua0[kstep * 8 + 8 * 132 + 4];
        const uint2* bp = Bf + (size_t)(kstep * 32 + ntb) * 32 + lane;
#pragma unroll
        for (int nt = 0; nt < 16; ++nt) {
            uint2 b = __ldg(bp + nt * 32);
            mma_bf16(acc[nt], a0, a1, a2, a3, b.x, b.y);
        }
    }
}

// ================= prep kernels =================
__global__ void hist_kernel(const int* __restrict__ ei) {
    int e = blockIdx.x * 256 + threadIdx.x;
    if (e < NE) atomicAdd(&g_deg[ei[e]], 1);
}
__global__ void scan_kernel() {
    __shared__ int part[256];
    int t = threadIdx.x;
    int base = t * 40;
    int s = 0;
    for (int j = 0; j < 40; ++j) {
        int i = base + j;
        if (i < NN) s += g_deg[i];
    }
    part[t] = s;
    __syncthreads();
    if (t == 0) {
        int run = 0;
        for (int i = 0; i < 256; ++i) { int v = part[i]; part[i] = run; run += v; }
    }
    __syncthreads();
    int run = part[t];
    for (int j = 0; j < 40; ++j) {
        int i = base + j;
        if (i < NN) { g_cur[i] = run; run += g_deg[i]; }
    }
}
__global__ void scatter_kernel(const int* __restrict__ ei, const float* __restrict__ ea) {
    int e = blockIdx.x * 256 + threadIdx.x;
    if (e >= NE) return;
    int r = ei[e];
    int pos = atomicAdd(&g_cur[r], 1);
    g_srow[pos] = r;
    g_scol[pos] = ei[NE + e];
    g_sea[pos] = ((const float2*)ea)[e];
}

// fragment-pack all 15 weight matrices in one launch.
// frag index i: r=i&1, lane=(i>>1)&31, nt=(i>>6)&31, kstep=i>>11 (0..15)
// k = kstep*16 + 2*tig + 8*r ; n = nt*8 + g
struct WPtrs { const float* w[15]; };
__global__ void wfprep_all(WPtrs ptrs) {
    int m = blockIdx.x >> 7;
    int i = (blockIdx.x & 127) * 256 + threadIdx.x;   // 0..32767
    const float* W = ptrs.w[m];
    int r = i & 1, lane = (i >> 1) & 31, nt = (i >> 6) & 31, kstep = i >> 11;
    int g = lane >> 2, tig = lane & 3;
    int k = kstep * 16 + 2 * tig + 8 * r;
    int n = nt * 8 + g;
    g_WF[m * 32768 + i] = pack2(W[k * H + n], W[(k + 1) * H + n]);
}

// ================= node GEMM: bf16 mma, direct-gmem B fragments =================
// C[M,256] = [act](A1@B1 [+ A2@B2] + bias) [+ resid]
__global__ __launch_bounds__(256, 2) void node_mma(
    const float* __restrict__ A1, const uint2* __restrict__ B1f,
    const float* __restrict__ A2, const uint2* __restrict__ B2f,
    const float* __restrict__ bias, const float* __restrict__ resid,
    float* __restrict__ C, int M, int act) {
    __shared__ uint32_t u_s[64 * 132];
    int tid = threadIdx.x, wid = tid >> 5, lane = tid & 31;
    int m0 = blockIdx.x * 64;
    int r0 = (wid >> 1) * 16, ntb = (wid & 1) * 16;

    float acc[16][4] = {};
    int npass = A2 ? 2 : 1;
    for (int pass = 0; pass < npass; ++pass) {
        const float* A = pass ? A2 : A1;
        const uint2* Bf = pass ? B2f : B1f;
        __syncthreads();
#pragma unroll 4
        for (int it = 0; it < 16; ++it) {
            int idx = it * 256 + tid;
            int e = idx >> 6;
            int kq = (idx & 63) << 2;
            int row = min(m0 + e, M - 1);
            float4 v = *(const float4*)&A[(size_t)row * H + kq];
            uint2 w;
            w.x = pack2(v.x, v.y);
            w.y = pack2(v.z, v.w);
            *(uint2*)&u_s[e * 132 + (kq >> 1)] = w;
        }
        __syncthreads();
        mma_block_direct(u_s, Bf, r0, ntb, lane, acc);
    }

    int g = lane >> 2, tig = lane & 3;
    int row0 = m0 + r0 + g, row1 = row0 + 8;
#pragma unroll
    for (int nt = 0; nt < 16; ++nt) {
        int col = (ntb + nt) * 8 + 2 * tig;
        float b0v = 0.f, b1v = 0.f;
        if (bias) { b0v = bias[col]; b1v = bias[col + 1]; }
        float v00 = acc[nt][0] + b0v, v01 = acc[nt][1] + b1v;
        float v10 = acc[nt][2] + b0v, v11 = acc[nt][3] + b1v;
        if (act) { v00 = siluf(v00); v01 = siluf(v01); v10 = siluf(v10); v11 = siluf(v11); }
        if (row0 < M) {
            if (resid) {
                float2 rv = *(const float2*)&resid[(size_t)row0 * H + col];
                v00 += rv.x; v01 += rv.y;
            }
            *(float2*)&C[(size_t)row0 * H + col] = make_float2(v00, v01);
        }
        if (row1 < M) {
            if (resid) {
                float2 rv = *(const float2*)&resid[(size_t)row1 * H + col];
                v10 += rv.x; v11 += rv.y;
            }
            *(float2*)&C[(size_t)row1 * H + col] = make_float2(v10, v11);
        }
    }
}

// ================= edge kernel =================
// smem (u32 units)
#define EU   0        // u/mij tile: 64 rows x 132 words (bf16 pairs)
#define EPS  8448     // float ps[64]
#define EATT 8512     // float att[64]
#define EB2  8576     // float b2s[256]
#define EWV  8832     // float wvs[256]
#define ESR  9088     // int srow[64]
#define ESC  9152     // int scol[64]
#define EEA  9216     // float eas[128]
#define ETOT 9344
#define EDGE_SMEM (ETOT * 4)

template <bool COORD>
__global__ __launch_bounds__(256, 2) void edge_bf16_kernel(
    const float* __restrict__ Pa, const float* __restrict__ Pb,
    const float* __restrict__ wtail, const float* __restrict__ b1,
    const uint2* __restrict__ W2F, const float* __restrict__ b2,
    const float* __restrict__ wv, const float* __restrict__ ab,
    float* __restrict__ agg, const float* __restrict__ xg) {
    extern __shared__ uint32_t sm32[];
    float* ps    = (float*)(sm32 + EPS);
    float* att_s = (float*)(sm32 + EATT);
    float* b2s   = (float*)(sm32 + EB2);
    float* wvs   = (float*)(sm32 + EWV);
    int* srow_s  = (int*)(sm32 + ESR);
    int* scol_s  = (int*)(sm32 + ESC);
    float* eas   = (float*)(sm32 + EEA);

    int tid = threadIdx.x, wid = tid >> 5, lane = tid & 31;
    int g = lane >> 2, tig = lane & 3;
    int e0 = blockIdx.x * 64;
    int r0 = (wid >> 1) * 16, ntb = (wid & 1) * 16;

    if (tid < 64) {
        srow_s[tid] = g_srow[e0 + tid];
        scol_s[tid] = g_scol[e0 + tid];
        float2 a = g_sea[e0 + tid];
        eas[tid] = a.x;
        eas[64 + tid] = a.y;
        ps[tid] = 0.f;
    }
    b2s[tid] = b2[tid];
    wvs[tid] = wv[tid];
    __syncthreads();

    // phase A: u = silu(Pa[row]+Pb[col]+ea@wtail+b1) -> bf16 pairs
#pragma unroll 4
    for (int it = 0; it < 16; ++it) {
        int idx = it * 256 + tid;
        int e = idx >> 6;
        int kq = (idx & 63) << 2;
        int r = srow_s[e], cl = scol_s[e];
        float4 pa = *(const float4*)&Pa[(size_t)r * H + kq];
        float4 pb = *(const float4*)&Pb[(size_t)cl * H + kq];
        float4 w0 = *(const float4*)&wtail[kq];
        float4 w1 = *(const float4*)&wtail[H + kq];
        float4 bv = *(const float4*)&b1[kq];
        float a0 = eas[e], a1 = eas[64 + e];
        float t0 = siluf(pa.x + pb.x + a0 * w0.x + a1 * w1.x + bv.x);
        float t1 = siluf(pa.y + pb.y + a0 * w0.y + a1 * w1.y + bv.y);
        float t2 = siluf(pa.z + pb.z + a0 * w0.z + a1 * w1.z + bv.z);
        float t3 = siluf(pa.w + pb.w + a0 * w0.w + a1 * w1.w + bv.w);
        uint2 w;
        w.x = pack2(t0, t1);
        w.y = pack2(t2, t3);
        *(uint2*)&sm32[EU + e * 132 + (kq >> 1)] = w;
    }
    __syncthreads();

    // MMA: D[64,256] = u @ W2 (B fragments streamed from L2)
    float acc[16][4] = {};
    mma_block_direct(sm32 + EU, W2F, r0, ntb, lane, acc);
    __syncthreads();   // mma reads of u_s done before mij overwrites it

    // epilogue: silu + dot(wv)
    int row0 = r0 + g, row1 = row0 + 8;
    float p0 = 0.f, p1 = 0.f;
#pragma unroll
    for (int nt = 0; nt < 16; ++nt) {
        int col = (ntb + nt) * 8 + 2 * tig;
        float bb0 = b2s[col], bb1 = b2s[col + 1];
        float w0 = wvs[col], w1 = wvs[col + 1];
        float v00 = siluf(acc[nt][0] + bb0), v01 = siluf(acc[nt][1] + bb1);
        float v10 = siluf(acc[nt][2] + bb0), v11 = siluf(acc[nt][3] + bb1);
        if (!COORD) {
            sm32[EU + row0 * 132 + (ntb + nt) * 4 + tig] = pack2(v00, v01);
            sm32[EU + row1 * 132 + (ntb + nt) * 4 + tig] = pack2(v10, v11);
        }
        p0 += v00 * w0 + v01 * w1;
        p1 += v10 * w0 + v11 * w1;
    }
    atomicAdd(&ps[row0], p0);
    atomicAdd(&ps[row1], p1);
    __syncthreads();

    if (COORD) {
        if (tid < 64) {
            float phi = ps[tid] * 0.01f;
            int r = srow_s[tid], c = scol_s[tid];
            float dx = xg[r * 3 + 0] - xg[c * 3 + 0];
            float dy = xg[r * 3 + 1] - xg[c * 3 + 1];
            float dz = xg[r * 3 + 2] - xg[c * 3 + 2];
            float inv = 1.0f / (sqrtf(dx * dx + dy * dy + dz * dz + 1e-8f) + 1.0f);
            atomicAdd(&agg[(size_t)r * 3 + 0], dx * inv * phi);
            atomicAdd(&agg[(size_t)r * 3 + 1], dy * inv * phi);
            atomicAdd(&agg[(size_t)r * 3 + 2], dz * inv * phi);
        }
    } else {
        if (tid < 64) att_s[tid] = sigmf(ps[tid] + ab[0]) * 0.01f;
        __syncthreads();
        // segmented reduction over sorted rows: 8 slot-groups x 32 col-chunks of 8
        int cch = tid & 31;
        int s0 = (tid >> 5) * 8;
        float av[8] = {};
        int currow = srow_s[s0];
        for (int s = s0; s < s0 + 8; ++s) {
            int r = srow_s[s];
            if (r != currow) {
                float* dst = agg + (size_t)currow * H + cch * 8;
#pragma unroll
                for (int j = 0; j < 8; ++j) { atomicAdd(dst + j, av[j]); av[j] = 0.f; }
                currow = r;
            }
            float a = att_s[s];
            uint4 w4 = *(const uint4*)(sm32 + EU + s * 132 + cch * 4);
            float2 f;
            f = up2(w4.x); av[0] += f.x * a; av[1] += f.y * a;
            f = up2(w4.y); av[2] += f.x * a; av[3] += f.y * a;
            f = up2(w4.z); av[4] += f.x * a; av[5] += f.y * a;
            f = up2(w4.w); av[6] += f.x * a; av[7] += f.y * a;
        }
        float* dst = agg + (size_t)currow * H + cch * 8;
#pragma unroll
        for (int j = 0; j < 8; ++j) atomicAdd(dst + j, av[j]);
    }
}

__global__ void x_final_kernel(const float* __restrict__ x, const float* __restrict__ aggx,
                               float* __restrict__ out) {
    int i = blockIdx.x * blockDim.x + threadIdx.x;
    if (i < NN * 3) out[i] = x[i] + aggx[i];
}

// ================= launch =================
extern "C" void kernel_launch(void* const* d_in, const int* in_sizes, int n_in,
                              void* d_out, int out_size) {
    const float* h0 = (const float*)d_in[0];
    const float* x = (const float*)d_in[1];
    const int* ei = (const int*)d_in[2];
    const float* ea = (const float*)d_in[3];
    const float* p[2][10];
    for (int l = 0; l < 2; ++l)
        for (int i = 0; i < 10; ++i) p[l][i] = (const float*)d_in[4 + l * 10 + i];
    // p[l]: 0 ew1, 1 eb1, 2 ew2, 3 eb2, 4 nw1, 5 nb1, 6 nw2, 7 nb2, 8 aw, 9 ab
    const float* cw1 = (const float*)d_in[24];
    const float* cb1 = (const float*)d_in[25];
    const float* cw2 = (const float*)d_in[26];
    const float* cb2 = (const float*)d_in[27];
    const float* cw3 = (const float*)d_in[28];

    float* outh = (float*)d_out;
    float* outx = outh + (size_t)NN * H;

    float *Pa, *Pb, *agg, *q, *h1, *aggx;
    int* deg;
    unsigned* wf;
    cudaGetSymbolAddress((void**)&Pa, g_Pa);
    cudaGetSymbolAddress((void**)&Pb, g_Pb);
    cudaGetSymbolAddress((void**)&agg, g_agg);
    cudaGetSymbolAddress((void**)&q, g_q);
    cudaGetSymbolAddress((void**)&h1, g_h1);
    cudaGetSymbolAddress((void**)&aggx, g_aggx);
    cudaGetSymbolAddress((void**)&deg, g_deg);
    cudaGetSymbolAddress((void**)&wf, g_WF);

    cudaFuncSetAttribute(edge_bf16_kernel<false>, cudaFuncAttributeMaxDynamicSharedMemorySize, EDGE_SMEM);
    cudaFuncSetAttribute(edge_bf16_kernel<true>, cudaFuncAttributeMaxDynamicSharedMemorySize, EDGE_SMEM);

    int gnode = (NN + 63) / 64;

    // prep: edge counting-sort + fragment-packed weights
    cudaMemsetAsync(deg, 0, NN * sizeof(int), 0);
    hist_kernel<<<(NE + 255) / 256, 256>>>(ei);
    scan_kernel<<<1, 256>>>();
    scatter_kernel<<<(NE + 255) / 256, 256>>>(ei, ea);
    WPtrs wp;
    for (int l = 0; l < 2; ++l) {
        wp.w[l * 6 + 0] = p[l][0];             // ew1a
        wp.w[l * 6 + 1] = p[l][0] + 256 * H;   // ew1b
        wp.w[l * 6 + 2] = p[l][2];             // ew2
        wp.w[l * 6 + 3] = p[l][4];             // nw1a
        wp.w[l * 6 + 4] = p[l][4] + 256 * H;   // nw1b
        wp.w[l * 6 + 5] = p[l][6];             // nw2
    }
    wp.w[12] = cw1;
    wp.w[13] = cw1 + 256 * H;
    wp.w[14] = cw2;
    wfprep_all<<<15 * 128, 256>>>(wp);

    const uint2* WF = (const uint2*)wf;
#define WFM(m) (WF + (size_t)(m) * 16384)

    const float* hcur = h0;
    float* houts[2] = {h1, outh};
    for (int l = 0; l < 2; ++l) {
        node_mma<<<gnode, 256>>>(hcur, WFM(l * 6 + 0), nullptr, nullptr,
                                 nullptr, nullptr, Pa, NN, 0);
        node_mma<<<gnode, 256>>>(hcur, WFM(l * 6 + 1), nullptr, nullptr,
                                 nullptr, nullptr, Pb, NN, 0);
        cudaMemsetAsync(agg, 0, (size_t)NN * H * sizeof(float), 0);
        edge_bf16_kernel<false><<<NE / 64, 256, EDGE_SMEM>>>(
            Pa, Pb, p[l][0] + 512 * H, p[l][1], WFM(l * 6 + 2), p[l][3], p[l][8], p[l][9],
            agg, nullptr);
        node_mma<<<gnode, 256>>>(hcur, WFM(l * 6 + 3), agg, WFM(l * 6 + 4),
                                 p[l][5], nullptr, q, NN, 1);
        node_mma<<<gnode, 256>>>(q, WFM(l * 6 + 5), nullptr, nullptr,
                                 p[l][7], hcur, houts[l], NN, 0);
        hcur = houts[l];
    }

    node_mma<<<gnode, 256>>>(hcur, WFM(12), nullptr, nullptr, nullptr, nullptr, Pa, NN, 0);
    node_mma<<<gnode, 256>>>(hcur, WFM(13), nullptr, nullptr, nullptr, nullptr, Pb, NN, 0);
    cudaMemsetAsync(aggx, 0, (size_t)NN * 3 * sizeof(float), 0);
    edge_bf16_kernel<true><<<NE / 64, 256, EDGE_SMEM>>>(
        Pa, Pb, cw1 + 512 * H, cb1, WFM(14), cb2, cw3, nullptr, aggx, x);
    x_final_kernel<<<(NN * 3 + 255) / 256, 256>>>(x, aggx, outx);
}